// round 3
// baseline (speedup 1.0000x reference)
#include <cuda_runtime.h>

// Problem shape (fixed for this dataset entry)
#define BB 32
#define SS 4096
#define HH 512
#define AA 256

// Scratch (no allocations allowed -> __device__ globals)
__device__ float g_scores[BB * SS];            // pre-softmax logits
__device__ float g_decp[BB * AA];              // decoder projection (incl. b_dec)
__device__ float g_ctx_part[BB * 32 * HH];     // 32 S-chunks of partial context

// ---------------------------------------------------------------------------
// fast tanh: (e^{2x}-1)/(e^{2x}+1) with clamp; __expf -> MUFU.EX2 (~2e-6 rel)
// ---------------------------------------------------------------------------
__device__ __forceinline__ float fast_tanh(float x) {
    x = fminf(15.0f, fmaxf(-15.0f, x));
    float t = __expf(2.0f * x);
    return __fdividef(t - 1.0f, t + 1.0f);
}

// ---------------------------------------------------------------------------
// k0: dec_p[b][a] = decoder_hidden[b] . W_dec[:,a] + b_dec[a]
// grid(B), block(256): thread t owns column a = t
// ---------------------------------------------------------------------------
__global__ void dec_proj_kernel(const float* __restrict__ dh,
                                const float* __restrict__ Wdec,
                                const float* __restrict__ bdec) {
    __shared__ float sdh[HH];
    int b = blockIdx.x;
    int t = threadIdx.x;
    for (int k = t; k < HH; k += 256) sdh[k] = dh[b * HH + k];
    __syncthreads();
    float acc = bdec[t];
    #pragma unroll 8
    for (int k = 0; k < HH; k++) acc = fmaf(sdh[k], Wdec[k * AA + t], acc);
    g_decp[b * AA + t] = acc;
}

// ---------------------------------------------------------------------------
// k1: scores. Tiled fp32 GEMM [64 x 256] per CTA over K=512, fused epilogue:
//     score[row] = sum_a tanh(acc + b_enc[a] + dec_p[b][a]) * W_e[a]
// 256 threads: ty=tid/32 (8 row groups of 8), tx=tid%32 (col groups of 4+4)
// ---------------------------------------------------------------------------
#define BM 64
#define BK 32

__global__ __launch_bounds__(256) void scores_kernel(
    const float* __restrict__ enc,
    const float* __restrict__ Wenc,
    const float* __restrict__ benc,
    const float* __restrict__ We) {

    __shared__ float As[BK][BM + 4];   // transposed A tile, stride 68 floats (conflict-free)
    __shared__ float Bs[BK][AA];       // W_enc tile

    const int tid = threadIdx.x;
    const int ty = tid >> 5;           // 0..7
    const int tx = tid & 31;           // 0..31 (lane id)
    const int row0 = blockIdx.x * BM;  // 64 | 4096 -> CTA never crosses a batch
    const int batch = row0 / SS;

    float acc[8][8];
    #pragma unroll
    for (int i = 0; i < 8; i++)
        #pragma unroll
        for (int j = 0; j < 8; j++) acc[i][j] = 0.0f;

    for (int k0 = 0; k0 < HH; k0 += BK) {
        // --- load A tile: 64 rows x 32 k = 512 float4 (2 per thread) ---
        #pragma unroll
        for (int r = 0; r < 2; r++) {
            int idx = tid + r * 256;          // 0..511
            int m   = idx >> 3;               // row within tile (0..63)
            int k4  = idx & 7;                // which float4 in the 32-k slab
            float4 v = *(const float4*)&enc[(size_t)(row0 + m) * HH + k0 + k4 * 4];
            As[k4 * 4 + 0][m] = v.x;
            As[k4 * 4 + 1][m] = v.y;
            As[k4 * 4 + 2][m] = v.z;
            As[k4 * 4 + 3][m] = v.w;
        }
        // --- load B tile: 32 k x 256 a = 2048 float4 (8 per thread) ---
        #pragma unroll
        for (int r = 0; r < 8; r++) {
            int idx = tid + r * 256;          // 0..2047
            int kk  = idx >> 6;               // k row 0..31 (64 float4 per row)
            int a4  = idx & 63;
            *(float4*)&Bs[kk][a4 * 4] =
                *(const float4*)&Wenc[(size_t)(k0 + kk) * AA + a4 * 4];
        }
        __syncthreads();

        #pragma unroll 8
        for (int k = 0; k < BK; k++) {
            float4 a0 = *(const float4*)&As[k][ty * 8];
            float4 a1 = *(const float4*)&As[k][ty * 8 + 4];
            float4 b0 = *(const float4*)&Bs[k][tx * 4];         // cols tx*4..+3
            float4 b1 = *(const float4*)&Bs[k][128 + tx * 4];   // cols 128+tx*4..+3
            float av[8] = {a0.x, a0.y, a0.z, a0.w, a1.x, a1.y, a1.z, a1.w};
            float bv[8] = {b0.x, b0.y, b0.z, b0.w, b1.x, b1.y, b1.z, b1.w};
            #pragma unroll
            for (int i = 0; i < 8; i++)
                #pragma unroll
                for (int j = 0; j < 8; j++)
                    acc[i][j] = fmaf(av[i], bv[j], acc[i][j]);
        }
        __syncthreads();
    }

    // --- fused epilogue: bias + tanh + dot(W_e) + warp-reduce per row ---
    float bias[8], wv[8];
    #pragma unroll
    for (int j = 0; j < 8; j++) {
        int c = (j < 4) ? (tx * 4 + j) : (128 + tx * 4 + (j - 4));
        bias[j] = benc[c] + g_decp[batch * AA + c];
        wv[j]   = We[c];
    }
    #pragma unroll
    for (int i = 0; i < 8; i++) {
        float s = 0.0f;
        #pragma unroll
        for (int j = 0; j < 8; j++)
            s = fmaf(fast_tanh(acc[i][j] + bias[j]), wv[j], s);
        // row's 256 cols live entirely in this warp (ty fixed per warp)
        #pragma unroll
        for (int off = 16; off > 0; off >>= 1)
            s += __shfl_down_sync(0xffffffffu, s, off);
        if (tx == 0) g_scores[row0 + ty * 8 + i] = s;   // b_e omitted: softmax-invariant
    }
}

// ---------------------------------------------------------------------------
// k2: softmax over S per batch. grid(B), block(256). Writes attn to d_out.
// ---------------------------------------------------------------------------
__global__ void softmax_kernel(float* __restrict__ attn_out) {
    __shared__ float sv[SS];     // 16 KB
    __shared__ float red[8];
    int b = blockIdx.x, t = threadIdx.x;
    int warp = t >> 5, lane = t & 31;

    float m = -1e30f;
    for (int i = t; i < SS; i += 256) {
        float v = g_scores[b * SS + i];
        sv[i] = v;
        m = fmaxf(m, v);
    }
    #pragma unroll
    for (int off = 16; off > 0; off >>= 1)
        m = fmaxf(m, __shfl_down_sync(0xffffffffu, m, off));
    if (lane == 0) red[warp] = m;
    __syncthreads();
    if (t == 0) {
        float mm = red[0];
        #pragma unroll
        for (int w = 1; w < 8; w++) mm = fmaxf(mm, red[w]);
        red[0] = mm;
    }
    __syncthreads();
    m = red[0];
    __syncthreads();

    float sum = 0.0f;
    for (int i = t; i < SS; i += 256) {
        float e = __expf(sv[i] - m);
        sv[i] = e;
        sum += e;
    }
    #pragma unroll
    for (int off = 16; off > 0; off >>= 1)
        sum += __shfl_down_sync(0xffffffffu, sum, off);
    if (lane == 0) red[warp] = sum;
    __syncthreads();
    if (t == 0) {
        float ss = 0.0f;
        #pragma unroll
        for (int w = 0; w < 8; w++) ss += red[w];
        red[0] = 1.0f / ss;
    }
    __syncthreads();
    float inv = red[0];
    for (int i = t; i < SS; i += 256)
        attn_out[b * SS + i] = sv[i] * inv;
}

// ---------------------------------------------------------------------------
// k3: context partials. grid(32 s-chunks, B), block(H=512).
// Deterministic: partials to scratch, no float atomics.
// ---------------------------------------------------------------------------
__global__ void context_partial_kernel(const float* __restrict__ enc,
                                       const float* __restrict__ attn) {
    __shared__ float sa[128];
    int b  = blockIdx.y;
    int s0 = blockIdx.x * 128;
    int h  = threadIdx.x;
    if (h < 128) sa[h] = attn[b * SS + s0 + h];
    __syncthreads();
    const float* base = enc + ((size_t)b * SS + s0) * HH + h;
    float acc = 0.0f;
    #pragma unroll 4
    for (int s = 0; s < 128; s++)
        acc = fmaf(sa[s], base[(size_t)s * HH], acc);
    g_ctx_part[(b * 32 + blockIdx.x) * HH + h] = acc;
}

// k4: reduce 32 partials -> context in d_out. grid(B), block(512).
__global__ void context_reduce_kernel(float* __restrict__ ctx_out) {
    int b = blockIdx.x, h = threadIdx.x;
    float acc = 0.0f;
    #pragma unroll
    for (int sc = 0; sc < 32; sc++)
        acc += g_ctx_part[(b * 32 + sc) * HH + h];
    ctx_out[b * HH + h] = acc;
}

// ---------------------------------------------------------------------------
// entry point
// inputs: 0=encoder_outputs 1=decoder_hidden 2=W_enc 3=b_enc 4=W_dec 5=b_dec
//         6=W_e 7=b_e   output: [context(B*H) , attn(B*S)]
// ---------------------------------------------------------------------------
extern "C" void kernel_launch(void* const* d_in, const int* in_sizes, int n_in,
                              void* d_out, int out_size) {
    const float* enc  = (const float*)d_in[0];
    const float* dh   = (const float*)d_in[1];
    const float* Wenc = (const float*)d_in[2];
    const float* benc = (const float*)d_in[3];
    const float* Wdec = (const float*)d_in[4];
    const float* bdec = (const float*)d_in[5];
    const float* We   = (const float*)d_in[6];

    float* ctx_out  = (float*)d_out;             // [B, H]
    float* attn_out = (float*)d_out + BB * HH;   // [B, S]

    dec_proj_kernel<<<BB, 256>>>(dh, Wdec, bdec);
    scores_kernel<<<(BB * SS) / BM, 256>>>(enc, Wenc, benc, We);
    softmax_kernel<<<BB, 256>>>(attn_out);
    context_partial_kernel<<<dim3(32, BB), HH>>>(enc, attn_out);
    context_reduce_kernel<<<BB, HH>>>(ctx_out);
}

// round 5
// speedup vs baseline: 3.2383x; 3.2383x over previous
#include <cuda_runtime.h>
#include <cuda_bf16.h>
#include <cstdint>

// Problem shape (fixed)
#define BB 32
#define SS 4096
#define HH 512
#define AA 256

#define TM 128              // rows per CTA
#define KC 64               // K per chunk
#define NCH (HH / KC)       // 8 chunks

// ---------------- scratch (no allocs allowed) ----------------
__device__ float g_scores[BB * SS];
__device__ float g_decp[BB * AA];
__device__ float g_ctx_part[BB * 32 * HH];
// W_enc^T split to bf16 hi/lo, [n=256][k=512] row-major (k contiguous)
__device__ __nv_bfloat16 g_Bh[AA * HH];
__device__ __nv_bfloat16 g_Bl[AA * HH];

// ---------------- helpers ----------------
__device__ __forceinline__ uint32_t smem_u32(const void* p) {
    uint32_t a;
    asm("{ .reg .u64 t; cvta.to.shared.u64 t, %1; cvt.u32.u64 %0, t; }"
        : "=r"(a) : "l"(p));
    return a;
}

__device__ __forceinline__ float fast_tanh(float x) {
    x = fminf(15.0f, fmaxf(-15.0f, x));
    float t = __expf(2.0f * x);
    return __fdividef(t - 1.0f, t + 1.0f);
}

__device__ __forceinline__ void ldm_x4(uint32_t* r, uint32_t addr) {
    asm volatile("ldmatrix.sync.aligned.m8n8.x4.shared.b16 {%0,%1,%2,%3}, [%4];"
                 : "=r"(r[0]), "=r"(r[1]), "=r"(r[2]), "=r"(r[3]) : "r"(addr));
}

__device__ __forceinline__ void mma16816(float* d, const uint32_t* a, const uint32_t* b) {
    asm volatile(
        "mma.sync.aligned.m16n8k16.row.col.f32.bf16.bf16.f32 "
        "{%0,%1,%2,%3}, {%4,%5,%6,%7}, {%8,%9}, {%0,%1,%2,%3};"
        : "+f"(d[0]), "+f"(d[1]), "+f"(d[2]), "+f"(d[3])
        : "r"(a[0]), "r"(a[1]), "r"(a[2]), "r"(a[3]), "r"(b[0]), "r"(b[1]));
}

#define CP16(dst, src) \
    asm volatile("cp.async.ca.shared.global [%0], [%1], 16;" :: "r"(dst), "l"(src) : "memory")
#define CP_COMMIT() asm volatile("cp.async.commit_group;" ::: "memory")
#define CP_WAIT0()  asm volatile("cp.async.wait_group 0;"  ::: "memory")

// ---------------------------------------------------------------------------
// prep: W_enc[k][n] -> g_Bh/g_Bl[n][k] bf16 hi/lo. grid(HH), block(AA).
// ---------------------------------------------------------------------------
__global__ void prep_B_kernel(const float* __restrict__ Wenc) {
    int k = blockIdx.x, n = threadIdx.x;
    float v = Wenc[k * AA + n];
    __nv_bfloat16 hi = __float2bfloat16(v);
    __nv_bfloat16 lo = __float2bfloat16(v - __bfloat162float(hi));
    g_Bh[n * HH + k] = hi;
    g_Bl[n * HH + k] = lo;
}

// ---------------------------------------------------------------------------
// k0: dec_p[b][a] = decoder_hidden[b] . W_dec[:,a] + b_dec[a]
// ---------------------------------------------------------------------------
__global__ void dec_proj_kernel(const float* __restrict__ dh,
                                const float* __restrict__ Wdec,
                                const float* __restrict__ bdec) {
    __shared__ float sdh[HH];
    int b = blockIdx.x, t = threadIdx.x;
    for (int k = t; k < HH; k += 256) sdh[k] = dh[b * HH + k];
    __syncthreads();
    float acc = bdec[t];
    #pragma unroll 8
    for (int k = 0; k < HH; k++) acc = fmaf(sdh[k], Wdec[k * AA + t], acc);
    g_decp[b * AA + t] = acc;
}

// ---------------------------------------------------------------------------
// k1: scores via mma.sync split-bf16. grid(1024), block(512).
// CTA tile 128x256, warp grid 4(M)x4(N), warp tile 32x64, K chunks of 64.
// smem rows padded to 144B (16B-aligned cp.async, conflict-free ldmatrix).
// ---------------------------------------------------------------------------
#define RSTRIDE 144                         // bytes per smem row (64 bf16 + pad)
#define SM_AH   0u
#define SM_AL   (SM_AH + 128u * RSTRIDE)    // 18432
#define SM_BH   (SM_AL + 128u * RSTRIDE)    // 36864
#define SM_BL   (SM_BH + 256u * RSTRIDE)    // 73728
#define SM_BIAS (SM_BL + 256u * RSTRIDE)    // 110592
#define SM_WE   (SM_BIAS + 1024u)
#define SM_RED  (SM_WE + 1024u)             // 128*4 floats
#define SM_TOT  (SM_RED + 2048u)            // 114688 bytes

__global__ __launch_bounds__(512) void scores_mma_kernel(
    const float* __restrict__ enc,
    const float* __restrict__ benc,
    const float* __restrict__ We) {

    extern __shared__ char smem[];
    const uint32_t sb = smem_u32(smem);
    const int tid  = threadIdx.x;
    const int wid  = tid >> 5;
    const int lane = tid & 31;
    const int wm = (wid & 3) * 32;          // warp row base
    const int wn = (wid >> 2) * 64;         // warp col base
    const int row0 = blockIdx.x * TM;       // 128 | 4096 -> never crosses batch
    const int batch = row0 / SS;

    float* sbias = (float*)(smem + SM_BIAS);
    float* swe   = (float*)(smem + SM_WE);
    float* red   = (float*)(smem + SM_RED);
    if (tid < AA) {
        sbias[tid] = benc[tid] + g_decp[batch * AA + tid];
        swe[tid]   = We[tid];
    }

    float acc[2][8][4];
    #pragma unroll
    for (int mt = 0; mt < 2; mt++)
        #pragma unroll
        for (int nt = 0; nt < 8; nt++)
            #pragma unroll
            for (int c = 0; c < 4; c++) acc[mt][nt][c] = 0.0f;

    // precomputed ldmatrix lane addressing
    const int a_r  = (lane & 7) + ((lane >> 3) & 1) * 8;  // row offset in 16x16 A mat
    const int a_k  = (lane >> 4) * 8;                     // k offset
    const int b_n  = (lane & 7) + (lane >> 4) * 8;        // n offset in B pair
    const int b_k  = ((lane >> 3) & 1) * 8;               // k offset

    for (int c = 0; c < NCH; c++) {
        // ---- B: cp.async 16B chunks, verbatim (pre-split layout) ----
        {
            const char* bh = (const char*)g_Bh;
            const char* bl = (const char*)g_Bl;
            #pragma unroll
            for (int i = 0; i < 4; i++) {
                int idx = tid + i * 512;        // 0..2047
                int n   = idx >> 3;             // row
                int ch  = idx & 7;              // 16B chunk in the 128B row
                size_t src = (size_t)(n * HH + c * KC + ch * 8) * 2;
                uint32_t dst = n * RSTRIDE + ch * 16;
                CP16(sb + SM_BH + dst, bh + src);
                CP16(sb + SM_BL + dst, bl + src);
            }
        }
        // ---- A: load fp32, split hi/lo, store to smem ----
        {
            const float* Ab = enc + (size_t)row0 * HH + c * KC;
            #pragma unroll
            for (int i = 0; i < 4; i++) {
                int idx = tid + i * 512;        // 0..2047 float4s
                int m   = idx >> 4;             // 16 float4 per row
                int k4  = (idx & 15) * 4;
                float4 v = *(const float4*)(Ab + (size_t)m * HH + k4);
                __nv_bfloat162 h01 = __floats2bfloat162_rn(v.x, v.y);
                __nv_bfloat162 h23 = __floats2bfloat162_rn(v.z, v.w);
                __nv_bfloat162 l01 = __floats2bfloat162_rn(
                    v.x - __bfloat162float(h01.x), v.y - __bfloat162float(h01.y));
                __nv_bfloat162 l23 = __floats2bfloat162_rn(
                    v.z - __bfloat162float(h23.x), v.w - __bfloat162float(h23.y));
                uint32_t off = m * RSTRIDE + k4 * 2;
                *(uint2*)(smem + SM_AH + off) = make_uint2(*(uint32_t*)&h01, *(uint32_t*)&h23);
                *(uint2*)(smem + SM_AL + off) = make_uint2(*(uint32_t*)&l01, *(uint32_t*)&l23);
            }
        }
        CP_COMMIT();
        CP_WAIT0();
        __syncthreads();

        // ---- compute: 4 ksteps of 16 ----
        #pragma unroll
        for (int ks = 0; ks < 4; ks++) {
            const int k0 = ks * 16;
            uint32_t ah[2][4], al[2][4];
            #pragma unroll
            for (int mt = 0; mt < 2; mt++) {
                uint32_t ra = (wm + mt * 16 + a_r) * RSTRIDE + (k0 + a_k) * 2;
                ldm_x4(ah[mt], sb + SM_AH + ra);
                ldm_x4(al[mt], sb + SM_AL + ra);
            }
            #pragma unroll
            for (int ntp = 0; ntp < 4; ntp++) {
                uint32_t rb = (wn + ntp * 16 + b_n) * RSTRIDE + (k0 + b_k) * 2;
                uint32_t bh[4], bl[4];
                ldm_x4(bh, sb + SM_BH + rb);
                ldm_x4(bl, sb + SM_BL + rb);
                #pragma unroll
                for (int mt = 0; mt < 2; mt++)
                    #pragma unroll
                    for (int h = 0; h < 2; h++) {
                        float* d = acc[mt][ntp * 2 + h];
                        mma16816(d, ah[mt], &bh[h * 2]);   // hi*hi
                        mma16816(d, ah[mt], &bl[h * 2]);   // hi*lo
                        mma16816(d, al[mt], &bh[h * 2]);   // lo*hi
                    }
            }
        }
        __syncthreads();
    }

    // ---- fused epilogue: tanh(+bias)*We, reduce over 256 cols ----
    const int wnidx = wid >> 2;
    #pragma unroll
    for (int mt = 0; mt < 2; mt++) {
        int r_lo = wm + mt * 16 + (lane >> 2);
        float s0 = 0.0f, s1 = 0.0f;
        #pragma unroll
        for (int nt = 0; nt < 8; nt++) {
            int col = wn + nt * 8 + (lane & 3) * 2;
            float w0 = swe[col], w1 = swe[col + 1];
            float bb0 = sbias[col], bb1 = sbias[col + 1];
            s0 = fmaf(fast_tanh(acc[mt][nt][0] + bb0), w0, s0);
            s0 = fmaf(fast_tanh(acc[mt][nt][1] + bb1), w1, s0);
            s1 = fmaf(fast_tanh(acc[mt][nt][2] + bb0), w0, s1);
            s1 = fmaf(fast_tanh(acc[mt][nt][3] + bb1), w1, s1);
        }
        s0 += __shfl_xor_sync(0xffffffffu, s0, 1);
        s0 += __shfl_xor_sync(0xffffffffu, s0, 2);
        s1 += __shfl_xor_sync(0xffffffffu, s1, 1);
        s1 += __shfl_xor_sync(0xffffffffu, s1, 2);
        if ((lane & 3) == 0) {
            red[r_lo * 4 + wnidx]       = s0;
            red[(r_lo + 8) * 4 + wnidx] = s1;
        }
    }
    __syncthreads();
    if (tid < TM) {
        const float* rp = red + tid * 4;
        g_scores[row0 + tid] = rp[0] + rp[1] + rp[2] + rp[3];  // b_e omitted: softmax-invariant
    }
}

// ---------------------------------------------------------------------------
// k2: softmax over S per batch. grid(B), block(256). Writes attn to d_out.
// ---------------------------------------------------------------------------
__global__ void softmax_kernel(float* __restrict__ attn_out) {
    __shared__ float sv[SS];
    __shared__ float red[8];
    int b = blockIdx.x, t = threadIdx.x;
    int warp = t >> 5, lane = t & 31;

    float m = -1e30f;
    for (int i = t; i < SS; i += 256) {
        float v = g_scores[b * SS + i];
        sv[i] = v;
        m = fmaxf(m, v);
    }
    #pragma unroll
    for (int off = 16; off > 0; off >>= 1)
        m = fmaxf(m, __shfl_down_sync(0xffffffffu, m, off));
    if (lane == 0) red[warp] = m;
    __syncthreads();
    if (t == 0) {
        float mm = red[0];
        #pragma unroll
        for (int w = 1; w < 8; w++) mm = fmaxf(mm, red[w]);
        red[0] = mm;
    }
    __syncthreads();
    m = red[0];
    __syncthreads();

    float sum = 0.0f;
    for (int i = t; i < SS; i += 256) {
        float e = __expf(sv[i] - m);
        sv[i] = e;
        sum += e;
    }
    #pragma unroll
    for (int off = 16; off > 0; off >>= 1)
        sum += __shfl_down_sync(0xffffffffu, sum, off);
    if (lane == 0) red[warp] = sum;
    __syncthreads();
    if (t == 0) {
        float ss = 0.0f;
        #pragma unroll
        for (int w = 0; w < 8; w++) ss += red[w];
        red[0] = 1.0f / ss;
    }
    __syncthreads();
    float inv = red[0];
    for (int i = t; i < SS; i += 256)
        attn_out[b * SS + i] = sv[i] * inv;
}

// ---------------------------------------------------------------------------
// k3/k4: context, deterministic 2-stage
// ---------------------------------------------------------------------------
__global__ void context_partial_kernel(const float* __restrict__ enc,
                                       const float* __restrict__ attn) {
    __shared__ float sa[128];
    int b  = blockIdx.y;
    int s0 = blockIdx.x * 128;
    int h  = threadIdx.x;
    if (h < 128) sa[h] = attn[b * SS + s0 + h];
    __syncthreads();
    const float* base = enc + ((size_t)b * SS + s0) * HH + h;
    float acc = 0.0f;
    #pragma unroll 16
    for (int s = 0; s < 128; s++)
        acc = fmaf(sa[s], base[(size_t)s * HH], acc);
    g_ctx_part[(b * 32 + blockIdx.x) * HH + h] = acc;
}

__global__ void context_reduce_kernel(float* __restrict__ ctx_out) {
    int b = blockIdx.x, h = threadIdx.x;
    float acc = 0.0f;
    #pragma unroll
    for (int sc = 0; sc < 32; sc++)
        acc += g_ctx_part[(b * 32 + sc) * HH + h];
    ctx_out[b * HH + h] = acc;
}

// ---------------------------------------------------------------------------
// entry point
// ---------------------------------------------------------------------------
extern "C" void kernel_launch(void* const* d_in, const int* in_sizes, int n_in,
                              void* d_out, int out_size) {
    const float* enc  = (const float*)d_in[0];
    const float* dh   = (const float*)d_in[1];
    const float* Wenc = (const float*)d_in[2];
    const float* benc = (const float*)d_in[3];
    const float* Wdec = (const float*)d_in[4];
    const float* bdec = (const float*)d_in[5];
    const float* We   = (const float*)d_in[6];

    float* ctx_out  = (float*)d_out;             // [B, H]
    float* attn_out = (float*)d_out + BB * HH;   // [B, S]

    cudaFuncSetAttribute(scores_mma_kernel,
                         cudaFuncAttributeMaxDynamicSharedMemorySize, SM_TOT);

    prep_B_kernel<<<HH, AA>>>(Wenc);
    dec_proj_kernel<<<BB, 256>>>(dh, Wdec, bdec);
    scores_mma_kernel<<<(BB * SS) / TM, 512, SM_TOT>>>(enc, benc, We);
    softmax_kernel<<<BB, 256>>>(attn_out);
    context_partial_kernel<<<dim3(32, BB), HH>>>(enc, attn_out);
    context_reduce_kernel<<<BB, HH>>>(ctx_out);
}